// round 7
// baseline (speedup 1.0000x reference)
#include <cuda_runtime.h>
#include <cstdint>

#define BB 64
#define TT 512
#define DD 1024
#define KK 32
#define BTK (BB*TT*KK)

// scratch (allowed: __device__ globals, no allocation) — 16B-aligned logits copy
__device__ __align__(16) float g_scratch_logits[BTK];
__device__ float g_spart[BB];
__device__ int   g_msum[BB];

// ---------------------------------------------------------------------------
// helpers
// ---------------------------------------------------------------------------
__device__ __forceinline__ void cpa16(void* dst, const void* src) {
    unsigned s = (unsigned)__cvta_generic_to_shared(dst);
    asm volatile("cp.async.cg.shared.global [%0], [%1], 16;\n" :: "r"(s), "l"(src));
}
__device__ __forceinline__ void cpa_commit() { asm volatile("cp.async.commit_group;\n"); }
template<int N> __device__ __forceinline__ void cpa_wait() {
    asm volatile("cp.async.wait_group %0;\n" :: "n"(N));
}

typedef unsigned long long ull;
__device__ __forceinline__ ull fma2(ull a, ull b, ull c) {
    ull d; asm("fma.rn.f32x2 %0, %1, %2, %3;" : "=l"(d) : "l"(a), "l"(b), "l"(c));
    return d;
}
__device__ __forceinline__ ull add2(ull a, ull b) {
    ull d; asm("add.rn.f32x2 %0, %1, %2;" : "=l"(d) : "l"(a), "l"(b));
    return d;
}
__device__ __forceinline__ ull pack2(float lo, float hi) {
    ull d; asm("mov.b64 %0, {%1, %2};" : "=l"(d) : "f"(lo), "f"(hi));
    return d;
}
__device__ __forceinline__ float2 unpack2(ull v) {
    float2 f; asm("mov.b64 {%0, %1}, %2;" : "=f"(f.x), "=f"(f.y) : "l"(v));
    return f;
}

__device__ __forceinline__ float warpMaxf(float v) {
#pragma unroll
    for (int o = 16; o > 0; o >>= 1)
        v = fmaxf(v, __shfl_xor_sync(0xffffffffu, v, o));
    return v;
}
__device__ __forceinline__ float warpSumf(float v) {
#pragma unroll
    for (int o = 16; o > 0; o >>= 1)
        v += __shfl_xor_sync(0xffffffffu, v, o);
    return v;
}
__device__ __forceinline__ int warpSumi(int v) {
#pragma unroll
    for (int o = 16; o > 0; o >>= 1)
        v += __shfl_xor_sync(0xffffffffu, v, o);
    return v;
}

// ---------------------------------------------------------------------------
// GEMM: logits[r*32+k] = sum_d V[r,d]*W[k,d] + bias[k]
// 256 threads / 8 warps, 16 rows per warp (128 rows/block), D chunks of 16,
// 4-stage cp.async pipeline, ONE barrier per chunk, packed fma.rn.f32x2.
// ---------------------------------------------------------------------------
#define GR 16            // rows per warp
#define GD 16            // d per chunk
#define GNCH (DD/GD)     // 64 chunks
#define GSTG 4

__global__ __launch_bounds__(256, 3) void gemm_kernel(
    const float* __restrict__ V, const float* __restrict__ W,
    const float* __restrict__ bias, float* __restrict__ out,
    float* __restrict__ outAligned, int dualStore)
{
    __shared__ __align__(16) float Vs[GSTG][128][GD];
    __shared__ __align__(16) float Ws[GSTG][32][20];   // stride 20: odd*4 -> conflict-free

    const int tid  = threadIdx.x;
    const int warp = tid >> 5;
    const int lane = tid & 31;
    const int rowBase = blockIdx.x * 128;

    ull acc[GR];
#pragma unroll
    for (int r = 0; r < GR; r++) acc[r] = 0ull;

    auto loadChunk = [&](int st, int c) {
        const int d0 = c * GD;
        // V: 128 rows x 16 floats = 512 float4 -> 2 per thread
#pragma unroll
        for (int p = 0; p < 2; p++) {
            int idx = p * 256 + tid;
            int r = idx >> 2, c4 = idx & 3;
            cpa16(&Vs[st][r][c4 * 4], &V[(size_t)(rowBase + r) * DD + d0 + c4 * 4]);
        }
        // W: 32 k x 16 floats = 128 float4 -> threads 0..127
        if (tid < 128) {
            int k = tid >> 2, c4 = tid & 3;
            cpa16(&Ws[st][k][c4 * 4], &W[(size_t)k * DD + d0 + c4 * 4]);
        }
        cpa_commit();
    };

    loadChunk(0, 0);
    loadChunk(1, 1);
    loadChunk(2, 2);

    for (int c = 0; c < GNCH; c++) {
        cpa_wait<2>();          // group c complete
        __syncthreads();        // all threads' waits passed; buf (c-1)&3 free
        if (c + 3 < GNCH) loadChunk((c + 3) & 3, c + 3);
        const int st = c & 3;

#pragma unroll
        for (int g = 0; g < 4; g++) {                 // dd = 4*g
            ulonglong2 wv = *(const ulonglong2*)&Ws[st][lane][g * 4];
#pragma unroll
            for (int r = 0; r < GR; r++) {
                ulonglong2 vv = *(const ulonglong2*)&Vs[st][warp * GR + r][g * 4];
                acc[r] = fma2(vv.x, wv.x, acc[r]);
                acc[r] = fma2(vv.y, wv.y, acc[r]);
            }
        }
    }

    const float bk = bias[lane];
#pragma unroll
    for (int r = 0; r < GR; r++) {
        float2 f = unpack2(acc[r]);
        float val = f.x + f.y + bk;
        size_t idx = (size_t)(rowBase + warp * GR + r) * KK + lane;
        outAligned[idx] = val;
        if (dualStore) out[idx] = val;
    }
}

// ---------------------------------------------------------------------------
// CRF forward + gold-path score. One warp per batch; lane j = state j.
// Scaled-probability recurrence. Per step: STS a -> syncwarp -> 8x LDS.128 of
// a-vector -> 16 packed FFMA2 dot -> masked update. Per chunk (16 steps):
// single chunk max, lazy exp, popcount-based cl, one renorm.
// ---------------------------------------------------------------------------
__global__ __launch_bounds__(32) void crf_kernel(
    const float* __restrict__ L,       // logits [B,T,K] (16B aligned)
    const int*   __restrict__ mask,    // [B,T]
    const int*   __restrict__ targets, // [B,T]
    const float* __restrict__ trans,   // [K,K]
    const float* __restrict__ startT,  // [K]
    const float* __restrict__ endT)    // [K]
{
    __shared__ __align__(16) float Ls[2][16 * 32];   // 2 x 2KB logits staging
    __shared__ __align__(16) float a_sh[2][32];      // double-buffered alpha

    const int b = blockIdx.x;
    const int j = threadIdx.x;
    const unsigned FULL = 0xffffffffu;

    // packed E column j: ep[p] = (exp(trans[2p][j]), exp(trans[2p+1][j]))
    ull ep[16];
#pragma unroll
    for (int p = 0; p < 16; p++) {
        float e0 = __expf(trans[(2 * p) * KK + j]);
        float e1 = __expf(trans[(2 * p + 1) * KK + j]);
        ep[p] = pack2(e0, e1);
    }

    const float* Lb = L + (size_t)b * TT * KK;
    const int*   mb = mask + (size_t)b * TT;

    // mask bits, replicated per lane via ballot
    unsigned mbits[16];
#pragma unroll
    for (int w = 0; w < 16; w++)
        mbits[w] = __ballot_sync(FULL, mb[w * 32 + j] != 0);

    auto loadChunk = [&](int buf, int c) {
        const float* src = Lb + (size_t)c * 16 * KK;
#pragma unroll
        for (int q = 0; q < 4; q++) {
            int idx = q * 32 + j;
            cpa16(&Ls[buf][idx * 4], src + idx * 4);
        }
        cpa_commit();
    };

    loadChunk(0, 0);
    loadChunk(1, 1);

    float a = 0.f, cl = 0.f;
    int abuf = 0;

    for (int c = 0; c < 32; c++) {
        cpa_wait<1>();
        __syncwarp();

        // read chunk logits, single chunk max
        float lg[16];
#pragma unroll
        for (int s = 0; s < 16; s++) lg[s] = Ls[c & 1][s * 32 + j];
        float mc = lg[0];
#pragma unroll
        for (int s = 1; s < 16; s++) mc = fmaxf(mc, lg[s]);
        mc = warpMaxf(mc);
        __syncwarp();
        if (c + 2 < 32) loadChunk(c & 1, c + 2);

        unsigned bits = (mbits[c >> 1] >> ((c & 1) * 16)) & 0xFFFFu;

        if (c == 0) {
            // init t = 0
            float s0v = startT[j] + lg[0];
            float mm = warpMaxf(s0v);
            a  = __expf(s0v - mm);
            cl = mm;
            a_sh[0][j] = a;
            abuf = 0;
        }

#pragma unroll
        for (int s = 0; s < 16; s++) {
            if (c == 0 && s == 0) continue;          // uniform, handled above
            __syncwarp();                            // prev STS visible
            float gg = __expf(lg[s] - mc);           // issued early, used late
            const ulonglong2* ap = (const ulonglong2*)a_sh[abuf];
            ull p0 = 0, p1 = 0, p2 = 0, p3 = 0;
#pragma unroll
            for (int i = 0; i < 8; i += 4) {
                ulonglong2 q0 = ap[i + 0];
                ulonglong2 q1 = ap[i + 1];
                ulonglong2 q2 = ap[i + 2];
                ulonglong2 q3 = ap[i + 3];
                p0 = fma2(q0.x, ep[2 * i + 0], p0);
                p0 = fma2(q0.y, ep[2 * i + 1], p0);
                p1 = fma2(q1.x, ep[2 * i + 2], p1);
                p1 = fma2(q1.y, ep[2 * i + 3], p1);
                p2 = fma2(q2.x, ep[2 * i + 4], p2);
                p2 = fma2(q2.y, ep[2 * i + 5], p2);
                p3 = fma2(q3.x, ep[2 * i + 6], p3);
                p3 = fma2(q3.y, ep[2 * i + 7], p3);
            }
            ull t = add2(add2(p0, p1), add2(p2, p3));
            float2 f = unpack2(t);
            float dot = f.x + f.y;
            if ((bits >> s) & 1u) a = dot * gg;
            a_sh[abuf ^ 1][j] = a;
            abuf ^= 1;
        }

        // cl accumulation: mc added once per masked-in step of this chunk
        unsigned effb = (c == 0) ? (bits & 0xFFFEu) : bits;
        cl += mc * (float)__popc(effb);

        // renorm once per chunk
        float Mx = warpMaxf(a);
        a = __fdividef(a, Mx);
        cl += __logf(Mx);
        a_sh[abuf][j] = a;       // own slot rewrite; visible after next syncwarp
    }

    // partition = cl + log(sum_j a_j * exp(end_j))
    float pe = a * __expf(endT[j]);
    float S  = warpSumf(pe);
    float partition = cl + __logf(S);

    // ---- gold path score ----
    float emit_s = 0.f, trans_s = 0.f;
    int msum = 0;
    for (int t = j; t < TT; t += 32) {
        int tg = targets[(size_t)b * TT + t];
        int mk = mb[t];
        float em = Lb[(size_t)t * KK + tg];
        emit_s += em * (float)mk;
        if (t >= 1) {
            int tgp = targets[(size_t)b * TT + t - 1];
            trans_s += trans[tgp * KK + tg] * (float)mk;
        }
        msum += mk;
    }
    emit_s  = warpSumf(emit_s);
    trans_s = warpSumf(trans_s);
    msum    = warpSumi(msum);

    if (j == 0) {
        int last = msum - 1;
        int t0 = targets[(size_t)b * TT];
        int tl = targets[(size_t)b * TT + last];
        float score = startT[t0] + emit_s + trans_s + endT[tl];
        g_spart[b] = score - partition;
        g_msum[b]  = msum;
    }
}

// ---------------------------------------------------------------------------
__global__ __launch_bounds__(32) void finish_kernel(float* __restrict__ out,
                                                    int writeLoss)
{
    const int j = threadIdx.x;
    float sp = g_spart[j] + g_spart[j + 32];
    int   ms = g_msum[j]  + g_msum[j + 32];
    sp = warpSumf(sp);
    ms = warpSumi(ms);
    if (j == 0 && writeLoss) out[0] = -sp / (float)ms;
}

// ---------------------------------------------------------------------------
extern "C" void kernel_launch(void* const* d_in, const int* in_sizes, int n_in,
                              void* d_out, int out_size)
{
    const float* V       = (const float*)d_in[0];
    const int*   mask    = (const int*)  d_in[1];
    const int*   targets = (const int*)  d_in[2];
    const float* W       = (const float*)d_in[3];
    const float* bias    = (const float*)d_in[4];
    const float* trans   = (const float*)d_in[5];
    const float* startT  = (const float*)d_in[6];
    const float* endT    = (const float*)d_in[7];
    float* out = (float*)d_out;

    void* p = nullptr;
    cudaGetSymbolAddress(&p, g_scratch_logits);
    float* scratch = (float*)p;

    const int loff = out_size - BTK;   // (loss, logits) concat
    float* outLogits;
    int dualStore;
    if (loff >= 0) {
        outLogits = out + loff;
        if ((((uintptr_t)outLogits) & 15u) == 0) {
            scratch = outLogits;            // aligned: single store stream
            dualStore = 0;
        } else {
            dualStore = 1;                  // unaligned: scratch + harness copy
        }
    } else {
        outLogits = scratch;
        dualStore = 0;
    }

    gemm_kernel<<<(BB * TT) / 128, 256>>>(V, W, bias, outLogits, scratch, dualStore);
    crf_kernel<<<BB, 32>>>(scratch, mask, targets, trans, startT, endT);
    finish_kernel<<<1, 32>>>(out, (loff >= 1) ? 1 : 0);
}

// round 8
// speedup vs baseline: 1.1271x; 1.1271x over previous
#include <cuda_runtime.h>
#include <cstdint>

#define BB 64
#define TT 512
#define DD 1024
#define KK 32
#define BTK (BB*TT*KK)

// scratch (allowed: __device__ globals, no allocation) — 16B-aligned logits copy
__device__ __align__(16) float g_scratch_logits[BTK];
__device__ float g_spart[BB];
__device__ int   g_msum[BB];

// ---------------------------------------------------------------------------
// helpers
// ---------------------------------------------------------------------------
__device__ __forceinline__ void cpa16(void* dst, const void* src) {
    unsigned s = (unsigned)__cvta_generic_to_shared(dst);
    asm volatile("cp.async.cg.shared.global [%0], [%1], 16;\n" :: "r"(s), "l"(src));
}
__device__ __forceinline__ void cpa_commit() { asm volatile("cp.async.commit_group;\n"); }
template<int N> __device__ __forceinline__ void cpa_wait() {
    asm volatile("cp.async.wait_group %0;\n" :: "n"(N));
}

typedef unsigned long long ull;
__device__ __forceinline__ ull fma2(ull a, ull b, ull c) {
    ull d; asm("fma.rn.f32x2 %0, %1, %2, %3;" : "=l"(d) : "l"(a), "l"(b), "l"(c));
    return d;
}
__device__ __forceinline__ ull add2(ull a, ull b) {
    ull d; asm("add.rn.f32x2 %0, %1, %2;" : "=l"(d) : "l"(a), "l"(b));
    return d;
}
__device__ __forceinline__ ull pack2(float lo, float hi) {
    ull d; asm("mov.b64 %0, {%1, %2};" : "=l"(d) : "f"(lo), "f"(hi));
    return d;
}
__device__ __forceinline__ float2 unpack2(ull v) {
    float2 f; asm("mov.b64 {%0, %1}, %2;" : "=f"(f.x), "=f"(f.y) : "l"(v));
    return f;
}

__device__ __forceinline__ float warpMaxf(float v) {
#pragma unroll
    for (int o = 16; o > 0; o >>= 1)
        v = fmaxf(v, __shfl_xor_sync(0xffffffffu, v, o));
    return v;
}
__device__ __forceinline__ float warpSumf(float v) {
#pragma unroll
    for (int o = 16; o > 0; o >>= 1)
        v += __shfl_xor_sync(0xffffffffu, v, o);
    return v;
}
__device__ __forceinline__ int warpSumi(int v) {
#pragma unroll
    for (int o = 16; o > 0; o >>= 1)
        v += __shfl_xor_sync(0xffffffffu, v, o);
    return v;
}

// ---------------------------------------------------------------------------
// GEMM: logits[r*32+k] = sum_d V[r,d]*W[k,d] + bias[k]
// 256 threads, tile 128 rows x 32 k. Per-thread 4x4 register tile:
//   rows rg+32i (rg=tid>>3), k = kg+8jj (kg=tid&7).
// D chunks of 16, 3-stage cp.async pipeline, one barrier per chunk.
// Per d-quad per thread: 4 V + 4 W LDS.128 -> 32 FFMA2 (crossbar << fma issue).
// Stride-20 rows: W banks kg*20 mod 32 = {0,20,8,28,16,4,24,12} conflict-free.
// ---------------------------------------------------------------------------
#define GVSTR 20
#define GNCH (DD/16)     // 64 chunks

__global__ __launch_bounds__(256, 2) void gemm_kernel(
    const float* __restrict__ V, const float* __restrict__ W,
    const float* __restrict__ bias, float* __restrict__ out,
    float* __restrict__ outAligned, int dualStore)
{
    __shared__ __align__(16) float Vs[3][128 * GVSTR];   // 3 x 10240 B
    __shared__ __align__(16) float Ws[3][32 * GVSTR];    // 3 x  2560 B

    const int tid = threadIdx.x;
    const int kg  = tid & 7;
    const int rg  = tid >> 3;
    const int rowBase = blockIdx.x * 128;

    ull acc[4][4];
#pragma unroll
    for (int i = 0; i < 4; i++)
#pragma unroll
        for (int jj = 0; jj < 4; jj++) acc[i][jj] = 0ull;

    auto loadChunk = [&](int st, int c) {
        const int d0 = c * 16;
        // V: 128 rows x 16 floats = 512 float4 -> 2 per thread
#pragma unroll
        for (int p = 0; p < 2; p++) {
            int idx = p * 256 + tid;
            int r = idx >> 2, c4 = idx & 3;
            cpa16(&Vs[st][r * GVSTR + c4 * 4],
                  &V[(size_t)(rowBase + r) * DD + d0 + c4 * 4]);
        }
        // W: 32 k x 16 floats = 128 float4 -> threads 0..127
        if (tid < 128) {
            int k = tid >> 2, c4 = tid & 3;
            cpa16(&Ws[st][k * GVSTR + c4 * 4],
                  &W[(size_t)k * DD + d0 + c4 * 4]);
        }
        cpa_commit();
    };

    loadChunk(0, 0);
    loadChunk(1, 1);

    for (int c = 0; c < GNCH; c++) {
        cpa_wait<1>();          // chunk c resident
        __syncthreads();        // everyone past wait; buf (c-1)%3 = (c+2)%3 free
        if (c + 2 < GNCH) loadChunk((c + 2) % 3, c + 2);
        else cpa_commit();      // pad: keep group arithmetic consistent
        const float* Vst = Vs[c % 3];
        const float* Wst = Ws[c % 3];

#pragma unroll
        for (int q = 0; q < 4; q++) {
            ulonglong2 wv[4], vv[4];
#pragma unroll
            for (int jj = 0; jj < 4; jj++)
                wv[jj] = *(const ulonglong2*)&Wst[(kg + 8 * jj) * GVSTR + q * 4];
#pragma unroll
            for (int i = 0; i < 4; i++)
                vv[i] = *(const ulonglong2*)&Vst[(rg + 32 * i) * GVSTR + q * 4];
#pragma unroll
            for (int i = 0; i < 4; i++)
#pragma unroll
                for (int jj = 0; jj < 4; jj++) {
                    acc[i][jj] = fma2(vv[i].x, wv[jj].x, acc[i][jj]);
                    acc[i][jj] = fma2(vv[i].y, wv[jj].y, acc[i][jj]);
                }
        }
    }

    float bk[4];
#pragma unroll
    for (int jj = 0; jj < 4; jj++) bk[jj] = bias[kg + 8 * jj];

#pragma unroll
    for (int i = 0; i < 4; i++)
#pragma unroll
        for (int jj = 0; jj < 4; jj++) {
            float2 f = unpack2(acc[i][jj]);
            float val = f.x + f.y + bk[jj];
            size_t idx = (size_t)(rowBase + rg + 32 * i) * KK + kg + 8 * jj;
            outAligned[idx] = val;
            if (dualStore) out[idx] = val;
        }
}

// ---------------------------------------------------------------------------
// CRF forward + gold-path score. 8 blocks x 256 threads; warp w <-> batch
// blockIdx.x*8+w  =>  2 scan-warps per SMSP interleave to hide LDS/sync latency.
// Per warp: scaled-probability recurrence, smem-staged logits (16-step chunks),
// packed FFMA2 dot, single chunk-max, popcount cl, one renorm per chunk.
// ---------------------------------------------------------------------------
__global__ __launch_bounds__(256) void crf_kernel(
    const float* __restrict__ L,       // logits [B,T,K] (16B aligned)
    const int*   __restrict__ mask,    // [B,T]
    const int*   __restrict__ targets, // [B,T]
    const float* __restrict__ trans,   // [K,K]
    const float* __restrict__ startT,  // [K]
    const float* __restrict__ endT)    // [K]
{
    __shared__ __align__(16) float Ls[8][2][16 * 32];   // per-warp staging, 32KB
    __shared__ __align__(16) float a_sh[8][2][32];      // per-warp alpha,   2KB

    const int wl = threadIdx.x >> 5;
    const int j  = threadIdx.x & 31;
    const int b  = blockIdx.x * 8 + wl;
    const unsigned FULL = 0xffffffffu;

    // packed E column j: ep[p] = (exp(trans[2p][j]), exp(trans[2p+1][j]))
    ull ep[16];
#pragma unroll
    for (int p = 0; p < 16; p++) {
        float e0 = __expf(trans[(2 * p) * KK + j]);
        float e1 = __expf(trans[(2 * p + 1) * KK + j]);
        ep[p] = pack2(e0, e1);
    }

    const float* Lb = L + (size_t)b * TT * KK;
    const int*   mb = mask + (size_t)b * TT;

    // mask bits, replicated per lane via ballot
    unsigned mbits[16];
#pragma unroll
    for (int w = 0; w < 16; w++)
        mbits[w] = __ballot_sync(FULL, mb[w * 32 + j] != 0);

    auto loadChunk = [&](int buf, int c) {
        const float* src = Lb + (size_t)c * 16 * KK;
#pragma unroll
        for (int q = 0; q < 4; q++) {
            int idx = q * 32 + j;
            cpa16(&Ls[wl][buf][idx * 4], src + idx * 4);
        }
        cpa_commit();
    };

    loadChunk(0, 0);
    loadChunk(1, 1);

    float a = 0.f, cl = 0.f;
    int abuf = 0;

    for (int c = 0; c < 32; c++) {
        cpa_wait<1>();
        __syncwarp();

        // read chunk logits, single chunk max
        float lg[16];
#pragma unroll
        for (int s = 0; s < 16; s++) lg[s] = Ls[wl][c & 1][s * 32 + j];
        float mc = lg[0];
#pragma unroll
        for (int s = 1; s < 16; s++) mc = fmaxf(mc, lg[s]);
        mc = warpMaxf(mc);
        __syncwarp();
        if (c + 2 < 32) loadChunk(c & 1, c + 2);
        else cpa_commit();                      // keep pending-group count stable

        unsigned bits = (mbits[c >> 1] >> ((c & 1) * 16)) & 0xFFFFu;

        if (c == 0) {
            // init t = 0
            float s0v = startT[j] + lg[0];
            float mm = warpMaxf(s0v);
            a  = __expf(s0v - mm);
            cl = mm;
            a_sh[wl][0][j] = a;
            abuf = 0;
        }

#pragma unroll
        for (int s = 0; s < 16; s++) {
            if (c == 0 && s == 0) continue;          // handled above
            __syncwarp();                            // prev STS visible
            float gg = __expf(lg[s] - mc);           // issued early, used late
            const ulonglong2* ap = (const ulonglong2*)a_sh[wl][abuf];
            ull p0 = 0, p1 = 0, p2 = 0, p3 = 0;
#pragma unroll
            for (int i = 0; i < 8; i += 4) {
                ulonglong2 q0 = ap[i + 0];
                ulonglong2 q1 = ap[i + 1];
                ulonglong2 q2 = ap[i + 2];
                ulonglong2 q3 = ap[i + 3];
                p0 = fma2(q0.x, ep[2 * i + 0], p0);
                p0 = fma2(q0.y, ep[2 * i + 1], p0);
                p1 = fma2(q1.x, ep[2 * i + 2], p1);
                p1 = fma2(q1.y, ep[2 * i + 3], p1);
                p2 = fma2(q2.x, ep[2 * i + 4], p2);
                p2 = fma2(q2.y, ep[2 * i + 5], p2);
                p3 = fma2(q3.x, ep[2 * i + 6], p3);
                p3 = fma2(q3.y, ep[2 * i + 7], p3);
            }
            ull t = add2(add2(p0, p1), add2(p2, p3));
            float2 f = unpack2(t);
            float dot = f.x + f.y;
            if ((bits >> s) & 1u) a = dot * gg;
            a_sh[wl][abuf ^ 1][j] = a;
            abuf ^= 1;
        }

        // cl: mc added once per masked-in step of this chunk
        unsigned effb = (c == 0) ? (bits & 0xFFFEu) : bits;
        cl += mc * (float)__popc(effb);

        // renorm once per chunk
        float Mx = warpMaxf(a);
        a = __fdividef(a, Mx);
        cl += __logf(Mx);
        a_sh[wl][abuf][j] = a;   // own slot rewrite; visible after next syncwarp
    }

    // partition = cl + log(sum_j a_j * exp(end_j))
    float pe = a * __expf(endT[j]);
    float S  = warpSumf(pe);
    float partition = cl + __logf(S);

    // ---- gold path score ----
    float emit_s = 0.f, trans_s = 0.f;
    int msum = 0;
    for (int t = j; t < TT; t += 32) {
        int tg = targets[(size_t)b * TT + t];
        int mk = mb[t];
        float em = Lb[(size_t)t * KK + tg];
        emit_s += em * (float)mk;
        if (t >= 1) {
            int tgp = targets[(size_t)b * TT + t - 1];
            trans_s += trans[tgp * KK + tg] * (float)mk;
        }
        msum += mk;
    }
    emit_s  = warpSumf(emit_s);
    trans_s = warpSumf(trans_s);
    msum    = warpSumi(msum);

    if (j == 0) {
        int last = msum - 1;
        int t0 = targets[(size_t)b * TT];
        int tl = targets[(size_t)b * TT + last];
        float score = startT[t0] + emit_s + trans_s + endT[tl];
        g_spart[b] = score - partition;
        g_msum[b]  = msum;
    }
}

// ---------------------------------------------------------------------------
__global__ __launch_bounds__(32) void finish_kernel(float* __restrict__ out,
                                                    int writeLoss)
{
    const int j = threadIdx.x;
    float sp = g_spart[j] + g_spart[j + 32];
    int   ms = g_msum[j]  + g_msum[j + 32];
    sp = warpSumf(sp);
    ms = warpSumi(ms);
    if (j == 0 && writeLoss) out[0] = -sp / (float)ms;
}

// ---------------------------------------------------------------------------
extern "C" void kernel_launch(void* const* d_in, const int* in_sizes, int n_in,
                              void* d_out, int out_size)
{
    const float* V       = (const float*)d_in[0];
    const int*   mask    = (const int*)  d_in[1];
    const int*   targets = (const int*)  d_in[2];
    const float* W       = (const float*)d_in[3];
    const float* bias    = (const float*)d_in[4];
    const float* trans   = (const float*)d_in[5];
    const float* startT  = (const float*)d_in[6];
    const float* endT    = (const float*)d_in[7];
    float* out = (float*)d_out;

    void* p = nullptr;
    cudaGetSymbolAddress(&p, g_scratch_logits);
    float* scratch = (float*)p;

    const int loff = out_size - BTK;   // (loss, logits) concat
    float* outLogits;
    int dualStore;
    if (loff >= 0) {
        outLogits = out + loff;
        if ((((uintptr_t)outLogits) & 15u) == 0) {
            scratch = outLogits;            // aligned: single store stream
            dualStore = 0;
        } else {
            dualStore = 1;                  // unaligned: scratch + harness copy
        }
    } else {
        outLogits = scratch;
        dualStore = 0;
    }

    gemm_kernel<<<(BB * TT) / 128, 256>>>(V, W, bias, outLogits, scratch, dualStore);
    crf_kernel<<<BB / 8, 256>>>(scratch, mask, targets, trans, startT, endT);
    finish_kernel<<<1, 32>>>(out, (loff >= 1) ? 1 : 0);
}

// round 9
// speedup vs baseline: 1.1568x; 1.0264x over previous
#include <cuda_runtime.h>
#include <cstdint>

#define BB 64
#define TT 512
#define DD 1024
#define KK 32
#define BTK (BB*TT*KK)

// scratch (allowed: __device__ globals, no allocation) — 16B-aligned logits copy
__device__ __align__(16) float g_scratch_logits[BTK];
__device__ float g_spart[BB];
__device__ int   g_msum[BB];

// ---------------------------------------------------------------------------
// helpers
// ---------------------------------------------------------------------------
__device__ __forceinline__ void cpa16(void* dst, const void* src) {
    unsigned s = (unsigned)__cvta_generic_to_shared(dst);
    asm volatile("cp.async.cg.shared.global [%0], [%1], 16;\n" :: "r"(s), "l"(src));
}
__device__ __forceinline__ void cpa_commit() { asm volatile("cp.async.commit_group;\n"); }
template<int N> __device__ __forceinline__ void cpa_wait() {
    asm volatile("cp.async.wait_group %0;\n" :: "n"(N));
}

typedef unsigned long long ull;
__device__ __forceinline__ ull fma2(ull a, ull b, ull c) {
    ull d; asm("fma.rn.f32x2 %0, %1, %2, %3;" : "=l"(d) : "l"(a), "l"(b), "l"(c));
    return d;
}
__device__ __forceinline__ ull add2(ull a, ull b) {
    ull d; asm("add.rn.f32x2 %0, %1, %2;" : "=l"(d) : "l"(a), "l"(b));
    return d;
}
__device__ __forceinline__ ull pack2(float lo, float hi) {
    ull d; asm("mov.b64 %0, {%1, %2};" : "=l"(d) : "f"(lo), "f"(hi));
    return d;
}
__device__ __forceinline__ float2 unpack2(ull v) {
    float2 f; asm("mov.b64 {%0, %1}, %2;" : "=f"(f.x), "=f"(f.y) : "l"(v));
    return f;
}

__device__ __forceinline__ float warpMaxf(float v) {
#pragma unroll
    for (int o = 16; o > 0; o >>= 1)
        v = fmaxf(v, __shfl_xor_sync(0xffffffffu, v, o));
    return v;
}
__device__ __forceinline__ float warpSumf(float v) {
#pragma unroll
    for (int o = 16; o > 0; o >>= 1)
        v += __shfl_xor_sync(0xffffffffu, v, o);
    return v;
}
__device__ __forceinline__ int warpSumi(int v) {
#pragma unroll
    for (int o = 16; o > 0; o >>= 1)
        v += __shfl_xor_sync(0xffffffffu, v, o);
    return v;
}

// ---------------------------------------------------------------------------
// GEMM: logits[r*32+k] = sum_d V[r,d]*W[k,d] + bias[k]
// 256 threads, tile 128 rows x 32 k. Per-thread 4x4 register tile:
//   rows rg+32i (rg=tid>>3), k = kg+8jj (kg=tid&7).
// D chunks of 32, 3-stage cp.async pipeline, ONE barrier per chunk (32 total).
// Per d-quad: 4 V + 4 W LDS.128 -> 32 FFMA2. Stride 36 floats (144B):
//   W lanes (kg 0..7) -> segments kg*16 mod 128: 8 distinct, conflict-free;
//   V lanes (4 distinct rg/warp) -> 4 distinct segments, conflict-free.
// ---------------------------------------------------------------------------
#define GDC 32           // d per chunk
#define GSTR 36          // smem row stride (floats)
#define GNCH (DD/GDC)    // 32 chunks

__global__ __launch_bounds__(256, 2) void gemm_kernel(
    const float* __restrict__ V, const float* __restrict__ W,
    const float* __restrict__ bias, float* __restrict__ out,
    float* __restrict__ outAligned, int dualStore)
{
    __shared__ __align__(16) float Vs[3][128 * GSTR];   // 3 x 18432 B
    __shared__ __align__(16) float Ws[3][32 * GSTR];    // 3 x  4608 B

    const int tid = threadIdx.x;
    const int kg  = tid & 7;
    const int rg  = tid >> 3;
    const int rowBase = blockIdx.x * 128;

    ull acc[4][4];
#pragma unroll
    for (int i = 0; i < 4; i++)
#pragma unroll
        for (int jj = 0; jj < 4; jj++) acc[i][jj] = 0ull;

    auto loadChunk = [&](int st, int c) {
        const int d0 = c * GDC;
        // V: 128 rows x 32 floats = 1024 float4 -> 4 per thread
#pragma unroll
        for (int p = 0; p < 4; p++) {
            int idx = p * 256 + tid;
            int r = idx >> 3, c4 = idx & 7;
            cpa16(&Vs[st][r * GSTR + c4 * 4],
                  &V[(size_t)(rowBase + r) * DD + d0 + c4 * 4]);
        }
        // W: 32 k x 32 floats = 256 float4 -> 1 per thread
        {
            int k = tid >> 3, c4 = tid & 7;
            cpa16(&Ws[st][k * GSTR + c4 * 4],
                  &W[(size_t)k * DD + d0 + c4 * 4]);
        }
        cpa_commit();
    };

    loadChunk(0, 0);
    loadChunk(1, 1);

    for (int c = 0; c < GNCH; c++) {
        cpa_wait<1>();          // chunk c resident
        __syncthreads();        // everyone past wait; buf (c+2)%3 free
        if (c + 2 < GNCH) loadChunk((c + 2) % 3, c + 2);
        else cpa_commit();      // pad: keep pending-group count consistent
        const float* Vst = Vs[c % 3];
        const float* Wst = Ws[c % 3];

#pragma unroll
        for (int q = 0; q < 8; q++) {
            ulonglong2 wv[4], vv[4];
#pragma unroll
            for (int jj = 0; jj < 4; jj++)
                wv[jj] = *(const ulonglong2*)&Wst[(kg + 8 * jj) * GSTR + q * 4];
#pragma unroll
            for (int i = 0; i < 4; i++)
                vv[i] = *(const ulonglong2*)&Vst[(rg + 32 * i) * GSTR + q * 4];
#pragma unroll
            for (int i = 0; i < 4; i++)
#pragma unroll
                for (int jj = 0; jj < 4; jj++) {
                    acc[i][jj] = fma2(vv[i].x, wv[jj].x, acc[i][jj]);
                    acc[i][jj] = fma2(vv[i].y, wv[jj].y, acc[i][jj]);
                }
        }
    }

    float bk[4];
#pragma unroll
    for (int jj = 0; jj < 4; jj++) bk[jj] = bias[kg + 8 * jj];

#pragma unroll
    for (int i = 0; i < 4; i++)
#pragma unroll
        for (int jj = 0; jj < 4; jj++) {
            float2 f = unpack2(acc[i][jj]);
            float val = f.x + f.y + bk[jj];
            size_t idx = (size_t)(rowBase + rg + 32 * i) * KK + kg + 8 * jj;
            outAligned[idx] = val;
            if (dualStore) out[idx] = val;
        }
}

// ---------------------------------------------------------------------------
// CRF forward + gold-path score. 32 blocks x 32 threads; each warp scans TWO
// batches (2*bid, 2*bid+1) interleaved: the two serial chains hide each
// other's LDS/FFMA latency, one __syncwarp per step serves both.
// Per batch: scaled-probability recurrence, smem-staged logits (16-step
// chunks), packed FFMA2 dot, single chunk-max, popcount cl, renorm per chunk.
// ---------------------------------------------------------------------------
__global__ __launch_bounds__(32) void crf_kernel(
    const float* __restrict__ L,       // logits [B,T,K] (16B aligned)
    const int*   __restrict__ mask,    // [B,T]
    const int*   __restrict__ targets, // [B,T]
    const float* __restrict__ trans,   // [K,K]
    const float* __restrict__ startT,  // [K]
    const float* __restrict__ endT)    // [K]
{
    __shared__ __align__(16) float Ls[2][2][16 * 32];  // [bat][buf][..] 8KB
    __shared__ __align__(16) float ash[2][2][32];      // [bat][pp][j]

    const int j  = threadIdx.x;
    const int b0 = blockIdx.x * 2;
    const int b1 = b0 + 1;
    const unsigned FULL = 0xffffffffu;

    // packed E column j: ep[p] = (exp(trans[2p][j]), exp(trans[2p+1][j]))
    ull ep[16];
#pragma unroll
    for (int p = 0; p < 16; p++) {
        float e0 = __expf(trans[(2 * p) * KK + j]);
        float e1 = __expf(trans[(2 * p + 1) * KK + j]);
        ep[p] = pack2(e0, e1);
    }

    const float* LA = L + (size_t)b0 * TT * KK;
    const float* LBp = L + (size_t)b1 * TT * KK;
    const int*   mA = mask + (size_t)b0 * TT;
    const int*   mB = mask + (size_t)b1 * TT;

    unsigned mbitsA[16], mbitsB[16];
#pragma unroll
    for (int w = 0; w < 16; w++) {
        mbitsA[w] = __ballot_sync(FULL, mA[w * 32 + j] != 0);
        mbitsB[w] = __ballot_sync(FULL, mB[w * 32 + j] != 0);
    }

    auto loadChunk = [&](int buf, int c) {
        const float* sA = LA  + (size_t)c * 512;
        const float* sB = LBp + (size_t)c * 512;
#pragma unroll
        for (int q = 0; q < 4; q++) {
            int idx = q * 32 + j;
            cpa16(&Ls[0][buf][idx * 4], sA + idx * 4);
            cpa16(&Ls[1][buf][idx * 4], sB + idx * 4);
        }
        cpa_commit();
    };

    loadChunk(0, 0);
    loadChunk(1, 1);

    float aA = 0.f, clA = 0.f, aB = 0.f, clB = 0.f;
    int abuf = 0;

    for (int c = 0; c < 32; c++) {
        cpa_wait<1>();
        __syncwarp();

        float lgA[16], lgB[16];
#pragma unroll
        for (int s = 0; s < 16; s++) {
            lgA[s] = Ls[0][c & 1][s * 32 + j];
            lgB[s] = Ls[1][c & 1][s * 32 + j];
        }
        float mcA = lgA[0], mcB = lgB[0];
#pragma unroll
        for (int s = 1; s < 16; s++) {
            mcA = fmaxf(mcA, lgA[s]);
            mcB = fmaxf(mcB, lgB[s]);
        }
        mcA = warpMaxf(mcA);
        mcB = warpMaxf(mcB);
        __syncwarp();
        if (c + 2 < 32) loadChunk(c & 1, c + 2);
        else cpa_commit();

        unsigned bitsA = (mbitsA[c >> 1] >> ((c & 1) * 16)) & 0xFFFFu;
        unsigned bitsB = (mbitsB[c >> 1] >> ((c & 1) * 16)) & 0xFFFFu;

        if (c == 0) {
            float sA0 = startT[j] + lgA[0];
            float sB0 = startT[j] + lgB[0];
            float mmA = warpMaxf(sA0);
            float mmB = warpMaxf(sB0);
            aA = __expf(sA0 - mmA); clA = mmA;
            aB = __expf(sB0 - mmB); clB = mmB;
            ash[0][0][j] = aA;
            ash[1][0][j] = aB;
            abuf = 0;
        }

#pragma unroll
        for (int s = 0; s < 16; s++) {
            if (c == 0 && s == 0) continue;
            __syncwarp();                          // prev STS (both chains) visible
            float ggA = __expf(lgA[s] - mcA);
            float ggB = __expf(lgB[s] - mcB);
            const ulonglong2* apA = (const ulonglong2*)ash[0][abuf];
            const ulonglong2* apB = (const ulonglong2*)ash[1][abuf];
            ull pA0 = 0, pA1 = 0, pB0 = 0, pB1 = 0;
#pragma unroll
            for (int i = 0; i < 8; i += 2) {
                ulonglong2 qA0 = apA[i + 0];
                ulonglong2 qB0 = apB[i + 0];
                ulonglong2 qA1 = apA[i + 1];
                ulonglong2 qB1 = apB[i + 1];
                pA0 = fma2(qA0.x, ep[2 * i + 0], pA0);
                pB0 = fma2(qB0.x, ep[2 * i + 0], pB0);
                pA0 = fma2(qA0.y, ep[2 * i + 1], pA0);
                pB0 = fma2(qB0.y, ep[2 * i + 1], pB0);
                pA1 = fma2(qA1.x, ep[2 * i + 2], pA1);
                pB1 = fma2(qB1.x, ep[2 * i + 2], pB1);
                pA1 = fma2(qA1.y, ep[2 * i + 3], pA1);
                pB1 = fma2(qB1.y, ep[2 * i + 3], pB1);
            }
            ull tA = add2(pA0, pA1);
            ull tB = add2(pB0, pB1);
            float2 fA = unpack2(tA);
            float2 fB = unpack2(tB);
            float dotA = fA.x + fA.y;
            float dotB = fB.x + fB.y;
            if ((bitsA >> s) & 1u) aA = dotA * ggA;
            if ((bitsB >> s) & 1u) aB = dotB * ggB;
            ash[0][abuf ^ 1][j] = aA;
            ash[1][abuf ^ 1][j] = aB;
            abuf ^= 1;
        }

        unsigned effA = (c == 0) ? (bitsA & 0xFFFEu) : bitsA;
        unsigned effB = (c == 0) ? (bitsB & 0xFFFEu) : bitsB;
        clA += mcA * (float)__popc(effA);
        clB += mcB * (float)__popc(effB);

        float MxA = warpMaxf(aA);
        float MxB = warpMaxf(aB);
        aA = __fdividef(aA, MxA); clA += __logf(MxA);
        aB = __fdividef(aB, MxB); clB += __logf(MxB);
        ash[0][abuf][j] = aA;
        ash[1][abuf][j] = aB;
    }

    // partitions
    float eT = __expf(endT[j]);
    float SA = warpSumf(aA * eT);
    float SB = warpSumf(aB * eT);
    float partA = clA + __logf(SA);
    float partB = clB + __logf(SB);

    // ---- gold path scores (both batches) ----
    float emA = 0.f, trA = 0.f, emB = 0.f, trB = 0.f;
    int msA = 0, msB = 0;
    for (int t = j; t < TT; t += 32) {
        int tgA = targets[(size_t)b0 * TT + t];
        int tgB = targets[(size_t)b1 * TT + t];
        int mkA = mA[t], mkB = mB[t];
        emA += LA[(size_t)t * KK + tgA] * (float)mkA;
        emB += LBp[(size_t)t * KK + tgB] * (float)mkB;
        if (t >= 1) {
            int tpA = targets[(size_t)b0 * TT + t - 1];
            int tpB = targets[(size_t)b1 * TT + t - 1];
            trA += trans[tpA * KK + tgA] * (float)mkA;
            trB += trans[tpB * KK + tgB] * (float)mkB;
        }
        msA += mkA; msB += mkB;
    }
    emA = warpSumf(emA); trA = warpSumf(trA); msA = warpSumi(msA);
    emB = warpSumf(emB); trB = warpSumf(trB); msB = warpSumi(msB);

    if (j == 0) {
        int lA = msA - 1, lB = msB - 1;
        int t0A = targets[(size_t)b0 * TT];
        int t0B = targets[(size_t)b1 * TT];
        int tlA = targets[(size_t)b0 * TT + lA];
        int tlB = targets[(size_t)b1 * TT + lB];
        g_spart[b0] = startT[t0A] + emA + trA + endT[tlA] - partA;
        g_spart[b1] = startT[t0B] + emB + trB + endT[tlB] - partB;
        g_msum[b0] = msA;
        g_msum[b1] = msB;
    }
}

// ---------------------------------------------------------------------------
__global__ __launch_bounds__(32) void finish_kernel(float* __restrict__ out,
                                                    int writeLoss)
{
    const int j = threadIdx.x;
    float sp = g_spart[j] + g_spart[j + 32];
    int   ms = g_msum[j]  + g_msum[j + 32];
    sp = warpSumf(sp);
    ms = warpSumi(ms);
    if (j == 0 && writeLoss) out[0] = -sp / (float)ms;
}

// ---------------------------------------------------------------------------
extern "C" void kernel_launch(void* const* d_in, const int* in_sizes, int n_in,
                              void* d_out, int out_size)
{
    const float* V       = (const float*)d_in[0];
    const int*   mask    = (const int*)  d_in[1];
    const int*   targets = (const int*)  d_in[2];
    const float* W       = (const float*)d_in[3];
    const float* bias    = (const float*)d_in[4];
    const float* trans   = (const float*)d_in[5];
    const float* startT  = (const float*)d_in[6];
    const float* endT    = (const float*)d_in[7];
    float* out = (float*)d_out;

    void* p = nullptr;
    cudaGetSymbolAddress(&p, g_scratch_logits);
    float* scratch = (float*)p;

    const int loff = out_size - BTK;   // (loss, logits) concat
    float* outLogits;
    int dualStore;
    if (loff >= 0) {
        outLogits = out + loff;
        if ((((uintptr_t)outLogits) & 15u) == 0) {
            scratch = outLogits;            // aligned: single store stream
            dualStore = 0;
        } else {
            dualStore = 1;                  // unaligned: scratch + harness copy
        }
    } else {
        outLogits = scratch;
        dualStore = 0;
    }

    gemm_kernel<<<(BB * TT) / 128, 256>>>(V, W, bias, outLogits, scratch, dualStore);
    crf_kernel<<<BB / 2, 32>>>(scratch, mask, targets, trans, startT, endT);
    finish_kernel<<<1, 32>>>(out, (loff >= 1) ? 1 : 0);
}